// round 5
// baseline (speedup 1.0000x reference)
#include <cuda_runtime.h>
#include <cuda_fp16.h>

#define NCH 256

// fp16 NHWC copies of the three feature maps.
// offsets (halves): L1=0, L2=33554432, L3=41943040, total 44040192 (88MB)
__device__ __half g_nhwc[44040192];

// Precomputed per-output-pixel geometry: 4 tap bases (element offset into
// g_nhwc, incl. level + batch) + 16 folded weights. 80B per pixel.
struct PixGeom { int base[4]; float w[16]; };
__device__ PixGeom g_geom[263424];   // supports N up to 256

// ---------------------------------------------------------------------------
// NCHW fp32 -> NHWC fp16 transpose. Tile = 64 channels x 32 cells.
__global__ void __launch_bounds__(256)
nchw_to_nhwc_fp16(const float* __restrict__ feat, size_t dst_off, int HW)
{
    __shared__ float tile[64][33];
    int cell0 = blockIdx.x * 32;
    int c0    = blockIdx.y * 64;
    int b     = blockIdx.z;
    int lane = threadIdx.x & 31;
    int wid  = threadIdx.x >> 5;
    const float* src = feat + (size_t)b * NCH * HW;
#pragma unroll
    for (int k = 0; k < 8; k++) {
        int r = wid + k * 8;
        tile[r][lane] = src[(size_t)(c0 + r) * HW + cell0 + lane];
    }
    __syncthreads();
    // write: thread -> (cell = t>>3, c8 = t&7), one 16B store of 8 channels
    int cell = threadIdx.x >> 3;
    int c8   = threadIdx.x & 7;
    uint4 u;
    __half2 h;
    h = __floats2half2_rn(tile[c8*8+0][cell], tile[c8*8+1][cell]); u.x = *(unsigned*)&h;
    h = __floats2half2_rn(tile[c8*8+2][cell], tile[c8*8+3][cell]); u.y = *(unsigned*)&h;
    h = __floats2half2_rn(tile[c8*8+4][cell], tile[c8*8+5][cell]); u.z = *(unsigned*)&h;
    h = __floats2half2_rn(tile[c8*8+6][cell], tile[c8*8+7][cell]); u.w = *(unsigned*)&h;
    size_t addr = ((size_t)b * HW + cell0 + cell) * NCH + c0 + c8 * 8;
    reinterpret_cast<uint4*>(g_nhwc + dst_off)[addr >> 3] = u;
}

// ---------------------------------------------------------------------------
// Geometry precompute: one thread per output pixel (all levels fused).
template <int P, int H, int W>
__device__ __forceinline__ void geom_level(const float* __restrict__ rois,
                                           int lvl_off, float scale,
                                           int gbase, int gpx, int npx)
{
    if (gpx >= npx) return;
    constexpr int pixels = P * P;
    int n  = gpx / pixels;
    int p  = gpx - n * pixels;
    int ph = p / P;
    int pw = p - ph * P;
    const float* r = rois + n * 5;
    int   bi = (int)r[0];
    float x1 = fmaf(r[1], scale, -0.5f);
    float y1 = fmaf(r[2], scale, -0.5f);
    float bw = (fmaf(r[3], scale, -0.5f) - x1) * (1.0f / (float)P);
    float bh = (fmaf(r[4], scale, -0.5f) - y1) * (1.0f / (float)P);
    PixGeom g;
#pragma unroll
    for (int iy = 0; iy < 2; iy++) {
#pragma unroll
        for (int ix = 0; ix < 2; ix++) {
            float yy = fmaf((float)ph + 0.25f + 0.5f * iy, bh, y1);
            float xx = fmaf((float)pw + 0.25f + 0.5f * ix, bw, x1);
            bool valid = (yy > -1.f) && (yy < (float)H) &&
                         (xx > -1.f) && (xx < (float)W);
            float yc = fminf(fmaxf(yy, 0.f), (float)(H - 1));
            float xc = fminf(fmaxf(xx, 0.f), (float)(W - 1));
            int y0 = (int)yc;
            int x0 = (int)xc;
            float wy1 = (y0 >= H - 1) ? 1.f : yc - (float)y0;
            float wx1 = (x0 >= W - 1) ? 1.f : xc - (float)x0;
            int ya = min(y0, H - 2);
            int xa = min(x0, W - 2);
            float ws = valid ? 0.25f : 0.f;
            int s = iy * 2 + ix;
            g.base[s] = lvl_off + (bi * H * W + ya * W + xa) * NCH;
            g.w[s*4+0] = (1.f - wy1) * (1.f - wx1) * ws;
            g.w[s*4+1] = (1.f - wy1) * wx1 * ws;
            g.w[s*4+2] = wy1 * (1.f - wx1) * ws;
            g.w[s*4+3] = wy1 * wx1 * ws;
        }
    }
    g_geom[gbase + gpx] = g;
}

__global__ void __launch_bounds__(256)
geom_kernel(const float* __restrict__ rois, int N)
{
    int t = blockIdx.x * 256 + threadIdx.x;
    int n1 = N * 784, n2 = N * 196, n3 = N * 49;
    if (t < n1)
        geom_level<28, 256, 256>(rois, 0, 0.25f, 0, t, n1);
    else if (t < n1 + n2)
        geom_level<14, 128, 128>(rois, 33554432, 0.125f, n1, t - n1, n2);
    else
        geom_level<7, 64, 64>(rois, 41943040, 0.0625f, n1 + n2, t - n1 - n2, n3);
}

// ---------------------------------------------------------------------------
// Gather: one warp = one output pixel, lanes cover 256 channels (8 fp16 each).
// Geometry comes from g_geom (5 broadcast 16B loads). 4 taps of each bilinear
// sample accumulate in half2 (HFMA2), widened to fp32 once per sample.

#define TAPH(ptr, wh, s0, s1, s2, s3) do {                                   \
    uint4 _v = __ldg(reinterpret_cast<const uint4*>(ptr));                   \
    const __half2* _h = reinterpret_cast<const __half2*>(&_v);               \
    s0 = __hfma2(wh, _h[0], s0); s1 = __hfma2(wh, _h[1], s1);                \
    s2 = __hfma2(wh, _h[2], s2); s3 = __hfma2(wh, _h[3], s3);                \
} while (0)

template <int P, int W>
__device__ __forceinline__ void gather_level(
    float* __restrict__ out_lvl, int gbase,
    int pxbase, int npx, float* __restrict__ sacc)
{
    constexpr int pixels = P * P;
    int tid  = threadIdx.x;
    int wid  = tid >> 5;
    int lane = tid & 31;

    for (int j = 0; j < 4; j++) {
        int pxl = j * 8 + wid;
        int gpx = pxbase + pxl;
        float acc[8] = {0.f,0.f,0.f,0.f,0.f,0.f,0.f,0.f};
        if (gpx < npx) {
            const PixGeom* gp = &g_geom[gbase + gpx];
            const float4* g4 = reinterpret_cast<const float4*>(gp);
            float4 q0 = __ldg(g4 + 0);   // bases (bit-cast)
            float4 q1 = __ldg(g4 + 1);   // w[0..3]
            float4 q2 = __ldg(g4 + 2);   // w[4..7]
            float4 q3 = __ldg(g4 + 3);   // w[8..11]
            float4 q4 = __ldg(g4 + 4);   // w[12..15]
            int b0 = __float_as_int(q0.x), b1 = __float_as_int(q0.y);
            int b2 = __float_as_int(q0.z), b3 = __float_as_int(q0.w);
            const __half* lbase = g_nhwc + lane * 8;
            float4 wq[4] = {q1, q2, q3, q4};
            int    bs[4] = {b0, b1, b2, b3};
#pragma unroll
            for (int s = 0; s < 4; s++) {
                const __half* f = lbase + bs[s];
                __half2 w00 = __float2half2_rn(wq[s].x);
                __half2 w01 = __float2half2_rn(wq[s].y);
                __half2 w10 = __float2half2_rn(wq[s].z);
                __half2 w11 = __float2half2_rn(wq[s].w);
                __half2 z = __float2half2_rn(0.f);
                __half2 s0 = z, s1 = z, s2 = z, s3 = z;
                TAPH(f,                 w00, s0, s1, s2, s3);
                TAPH(f + NCH,           w01, s0, s1, s2, s3);
                TAPH(f + W * NCH,       w10, s0, s1, s2, s3);
                TAPH(f + (W + 1) * NCH, w11, s0, s1, s2, s3);
                float2 f0 = __half22float2(s0);
                float2 f1 = __half22float2(s1);
                float2 f2 = __half22float2(s2);
                float2 f3 = __half22float2(s3);
                acc[0] += f0.x; acc[1] += f0.y;
                acc[2] += f1.x; acc[3] += f1.y;
                acc[4] += f2.x; acc[5] += f2.y;
                acc[6] += f3.x; acc[7] += f3.y;
            }
        }
        int col = pxl ^ lane;
#pragma unroll
        for (int i = 0; i < 8; i++)
            sacc[(lane * 8 + i) * 32 + col] = acc[i];
    }
    __syncthreads();

    int pxlane = tid & 31;
    int gpx = pxbase + pxlane;
    if (gpx < npx) {
        int n = gpx / pixels;
        int p = gpx - n * pixels;
        float* ob = out_lvl + (size_t)n * NCH * pixels + p;
        int c0 = (tid >> 5) * 32;
#pragma unroll
        for (int i = 0; i < 32; i++) {
            int c = c0 + i;
            ob[(size_t)c * pixels] = sacc[c * 32 + (pxlane ^ ((c >> 3) & 31))];
        }
    }
}

__global__ void __launch_bounds__(256, 6)
roi_gather_kernel(float* __restrict__ out, int N, int nb1, int nb2)
{
    __shared__ float sacc[NCH * 32];
    int blk = blockIdx.x;
    int n1 = N * 784, n2 = N * 196;
    if (blk < nb1) {
        gather_level<28, 256>(out, 0, blk * 32, n1, sacc);
    } else if (blk < nb1 + nb2) {
        float* o2 = out + (size_t)N * NCH * 784;
        gather_level<14, 128>(o2, n1, (blk - nb1) * 32, n2, sacc);
    } else {
        float* o3 = out + (size_t)N * NCH * (784 + 196);
        gather_level<7, 64>(o3, n1 + n2, (blk - nb1 - nb2) * 32, N * 49, sacc);
    }
}

// ---------------------------------------------------------------------------
extern "C" void kernel_launch(void* const* d_in, const int* in_sizes, int n_in,
                              void* d_out, int out_size)
{
    const float* feat1 = (const float*)d_in[0];  // (2,256,256,256)
    const float* feat2 = (const float*)d_in[1];  // (2,256,128,128)
    const float* feat3 = (const float*)d_in[2];  // (2,256,64,64)
    const float* rois  = (const float*)d_in[3];  // (N,5)
    float* out = (float*)d_out;

    const int N = in_sizes[3] / 5;

    // 1) geometry precompute (independent of transposes)
    int npx = N * (784 + 196 + 49);
    geom_kernel<<<(npx + 255) / 256, 256>>>(rois, N);

    // 2) transpose each level to fp16 NHWC scratch
    {
        dim3 g1(65536 / 32, 4, 2);
        nchw_to_nhwc_fp16<<<g1, 256>>>(feat1, 0ull, 65536);
        dim3 g2(16384 / 32, 4, 2);
        nchw_to_nhwc_fp16<<<g2, 256>>>(feat2, 33554432ull, 16384);
        dim3 g3(4096 / 32, 4, 2);
        nchw_to_nhwc_fp16<<<g3, 256>>>(feat3, 41943040ull, 4096);
    }

    // 3) fused gather over all three levels
    int nb1 = (N * 784 + 31) / 32;
    int nb2 = (N * 196 + 31) / 32;
    int nb3 = (N * 49  + 31) / 32;
    roi_gather_kernel<<<nb1 + nb2 + nb3, 256>>>(out, N, nb1, nb2);
}

// round 6
// speedup vs baseline: 1.1972x; 1.1972x over previous
#include <cuda_runtime.h>
#include <cuda_fp16.h>

#define NCH 256

// fp16 NHWC copies of the three feature maps.
// offsets (halves): L1=0, L2=33554432, L3=41943040, total 44040192 (88MB)
__device__ __half g_nhwc[44040192];

// ---------------------------------------------------------------------------
// Fused NCHW fp32 -> NHWC fp16 transpose, all 3 levels in one launch.
// Tile = 64 channels x 128 cells. Reads: float4 (512B dense per warp-row).
// Writes: one uint4 (8 fp16 channels) per thread per step.
// blockIdx.x = linear tile id across {level, batch, channel-group, cell-group}.
__global__ void __launch_bounds__(256)
nchw_to_nhwc_fused(const float* __restrict__ f1,
                   const float* __restrict__ f2,
                   const float* __restrict__ f3,
                   int nt1, int nt12)
{
    __shared__ float tile[64][129];   // 128 cells + 1 pad (2-way LDS worst case)

    int blk = blockIdx.x;
    const float* feat; size_t dst_off; int HW; int tl;
    if (blk < nt1)        { feat = f1; dst_off = 0ull;        HW = 65536; tl = blk; }
    else if (blk < nt12)  { feat = f2; dst_off = 33554432ull; HW = 16384; tl = blk - nt1; }
    else                  { feat = f3; dst_off = 41943040ull; HW = 4096;  tl = blk - nt12; }

    int tiles_per_img = (HW / 128) * 4;          // 4 channel groups of 64
    int b   = tl / tiles_per_img;
    int rem = tl - b * tiles_per_img;
    int c0    = (rem & 3) * 64;
    int cell0 = (rem >> 2) * 128;

    int lane = threadIdx.x & 31;
    int wid  = threadIdx.x >> 5;                 // 0..7
    const float* src = feat + ((size_t)b * NCH + c0) * HW + cell0;

    // load: each warp handles 8 channel rows; lane loads one float4 (4 cells)
#pragma unroll
    for (int k = 0; k < 8; k++) {
        int r = wid * 8 + k;                     // channel row 0..63
        float4 v = __ldg(reinterpret_cast<const float4*>(src + (size_t)r * HW) + lane);
        tile[r][lane * 4 + 0] = v.x;
        tile[r][lane * 4 + 1] = v.y;
        tile[r][lane * 4 + 2] = v.z;
        tile[r][lane * 4 + 3] = v.w;
    }
    __syncthreads();

    // store: 1024 items = 128 cells x 8 ch-octets; 4 per thread
    uint4* dst4 = reinterpret_cast<uint4*>(g_nhwc + dst_off);
#pragma unroll
    for (int it = 0; it < 4; it++) {
        int item = it * 256 + threadIdx.x;
        int cell = item >> 3;                    // 0..127
        int c8   = item & 7;                     // channel octet
        uint4 u;
        __half2 h;
        h = __floats2half2_rn(tile[c8*8+0][cell], tile[c8*8+1][cell]); u.x = *(unsigned*)&h;
        h = __floats2half2_rn(tile[c8*8+2][cell], tile[c8*8+3][cell]); u.y = *(unsigned*)&h;
        h = __floats2half2_rn(tile[c8*8+4][cell], tile[c8*8+5][cell]); u.z = *(unsigned*)&h;
        h = __floats2half2_rn(tile[c8*8+6][cell], tile[c8*8+7][cell]); u.w = *(unsigned*)&h;
        size_t addr = ((size_t)b * HW + cell0 + cell) * NCH + c0 + c8 * 8;
        dst4[addr >> 3] = u;
    }
}

// ---------------------------------------------------------------------------
// Gather (identical to the 123us R4 version): one warp = one output pixel,
// lanes cover 256 channels (8 fp16 each; one 16B load per tap). The 4 taps
// of each bilinear sample accumulate in half2 (HFMA2), widened to fp32 once
// per sample. Geometry recomputed in-kernel (registers, overlappable ALU).

#define TAPH(ptr, wh, s0, s1, s2, s3) do {                                   \
    uint4 _v = __ldg(reinterpret_cast<const uint4*>(ptr));                   \
    const __half2* _h = reinterpret_cast<const __half2*>(&_v);               \
    s0 = __hfma2(wh, _h[0], s0); s1 = __hfma2(wh, _h[1], s1);                \
    s2 = __hfma2(wh, _h[2], s2); s3 = __hfma2(wh, _h[3], s3);                \
} while (0)

template <int P, int H, int W>
__device__ __forceinline__ void gather_level(
    const float* __restrict__ rois, float* __restrict__ out_lvl,
    size_t lvl_off, float scale, int pxbase, int npx, float* __restrict__ sacc)
{
    constexpr int pixels = P * P;
    int tid  = threadIdx.x;
    int wid  = tid >> 5;
    int lane = tid & 31;

    for (int j = 0; j < 4; j++) {
        int pxl = j * 8 + wid;
        int gpx = pxbase + pxl;
        float acc[8] = {0.f,0.f,0.f,0.f,0.f,0.f,0.f,0.f};
        if (gpx < npx) {
            int n  = gpx / pixels;
            int p  = gpx - n * pixels;
            int ph = p / P;
            int pw = p - ph * P;
            const float* r = rois + n * 5;
            int   bi = (int)r[0];
            float x1 = fmaf(r[1], scale, -0.5f);
            float y1 = fmaf(r[2], scale, -0.5f);
            float bw = (fmaf(r[3], scale, -0.5f) - x1) * (1.0f / (float)P);
            float bh = (fmaf(r[4], scale, -0.5f) - y1) * (1.0f / (float)P);
            const __half* img = g_nhwc + lvl_off
                              + (size_t)bi * ((size_t)H * W) * NCH + lane * 8;
#pragma unroll
            for (int iy = 0; iy < 2; iy++) {
#pragma unroll
                for (int ix = 0; ix < 2; ix++) {
                    float yy = fmaf((float)ph + 0.25f + 0.5f * iy, bh, y1);
                    float xx = fmaf((float)pw + 0.25f + 0.5f * ix, bw, x1);
                    bool valid = (yy > -1.f) && (yy < (float)H) &&
                                 (xx > -1.f) && (xx < (float)W);
                    float yc = fminf(fmaxf(yy, 0.f), (float)(H - 1));
                    float xc = fminf(fmaxf(xx, 0.f), (float)(W - 1));
                    int y0 = (int)yc;
                    int x0 = (int)xc;
                    float wy1 = (y0 >= H - 1) ? 1.f : yc - (float)y0;
                    float wx1 = (x0 >= W - 1) ? 1.f : xc - (float)x0;
                    int ya = min(y0, H - 2);
                    int xa = min(x0, W - 2);
                    float ws  = valid ? 0.25f : 0.f;
                    __half2 w00 = __float2half2_rn((1.f - wy1) * (1.f - wx1) * ws);
                    __half2 w01 = __float2half2_rn((1.f - wy1) * wx1 * ws);
                    __half2 w10 = __float2half2_rn(wy1 * (1.f - wx1) * ws);
                    __half2 w11 = __float2half2_rn(wy1 * wx1 * ws);
                    const __half* f = img + (size_t)(ya * W + xa) * NCH;
                    __half2 z = __float2half2_rn(0.f);
                    __half2 s0 = z, s1 = z, s2 = z, s3 = z;
                    TAPH(f,                       w00, s0, s1, s2, s3);
                    TAPH(f + NCH,                 w01, s0, s1, s2, s3);
                    TAPH(f + (size_t)W * NCH,     w10, s0, s1, s2, s3);
                    TAPH(f + (size_t)(W+1) * NCH, w11, s0, s1, s2, s3);
                    float2 f0 = __half22float2(s0);
                    float2 f1 = __half22float2(s1);
                    float2 f2 = __half22float2(s2);
                    float2 f3 = __half22float2(s3);
                    acc[0] += f0.x; acc[1] += f0.y;
                    acc[2] += f1.x; acc[3] += f1.y;
                    acc[4] += f2.x; acc[5] += f2.y;
                    acc[6] += f3.x; acc[7] += f3.y;
                }
            }
        }
        int col = pxl ^ lane;
#pragma unroll
        for (int i = 0; i < 8; i++)
            sacc[(lane * 8 + i) * 32 + col] = acc[i];
    }
    __syncthreads();

    int pxlane = tid & 31;
    int gpx = pxbase + pxlane;
    if (gpx < npx) {
        int n = gpx / pixels;
        int p = gpx - n * pixels;
        float* ob = out_lvl + (size_t)n * NCH * pixels + p;
        int c0 = (tid >> 5) * 32;
#pragma unroll
        for (int i = 0; i < 32; i++) {
            int c = c0 + i;
            ob[(size_t)c * pixels] = sacc[c * 32 + (pxlane ^ ((c >> 3) & 31))];
        }
    }
}

__global__ void __launch_bounds__(256)
roi_gather_kernel(const float* __restrict__ rois, float* __restrict__ out,
                  int N, int nb1, int nb2)
{
    __shared__ float sacc[NCH * 32];
    int blk = blockIdx.x;
    if (blk < nb1) {
        gather_level<28, 256, 256>(rois, out, 0ull, 0.25f,
                                   blk * 32, N * 784, sacc);
    } else if (blk < nb1 + nb2) {
        float* o2 = out + (size_t)N * NCH * 784;
        gather_level<14, 128, 128>(rois, o2, 33554432ull, 0.125f,
                                   (blk - nb1) * 32, N * 196, sacc);
    } else {
        float* o3 = out + (size_t)N * NCH * (784 + 196);
        gather_level<7, 64, 64>(rois, o3, 41943040ull, 0.0625f,
                                (blk - nb1 - nb2) * 32, N * 49, sacc);
    }
}

// ---------------------------------------------------------------------------
extern "C" void kernel_launch(void* const* d_in, const int* in_sizes, int n_in,
                              void* d_out, int out_size)
{
    const float* feat1 = (const float*)d_in[0];  // (2,256,256,256)
    const float* feat2 = (const float*)d_in[1];  // (2,256,128,128)
    const float* feat3 = (const float*)d_in[2];  // (2,256,64,64)
    const float* rois  = (const float*)d_in[3];  // (N,5)
    float* out = (float*)d_out;

    const int N = in_sizes[3] / 5;

    // 1) fused transpose of all three levels to fp16 NHWC scratch
    //    tiles: level1 = (65536/128)*4*2 = 4096, level2 = 1024, level3 = 256
    int nt1 = 4096, nt2 = 1024, nt3 = 256;
    nchw_to_nhwc_fused<<<nt1 + nt2 + nt3, 256>>>(feat1, feat2, feat3,
                                                 nt1, nt1 + nt2);

    // 2) fused gather over all three levels
    int nb1 = (N * 784 + 31) / 32;
    int nb2 = (N * 196 + 31) / 32;
    int nb3 = (N * 49  + 31) / 32;
    roi_gather_kernel<<<nb1 + nb2 + nb3, 256>>>(rois, out, N, nb1, nb2);
}

// round 7
// speedup vs baseline: 1.2972x; 1.0835x over previous
#include <cuda_runtime.h>
#include <cuda_fp16.h>

#define NCH 256

// fp16 NHWC copies of the three feature maps.
// offsets (halves): L1=0, L2=33554432, L3=41943040, total 44040192 (88MB)
__device__ __half g_nhwc[44040192];

// ---------------------------------------------------------------------------
// NCHW fp32 -> NHWC fp16 transpose (R4 version: best measured).
// Tile = 64 channels x 32 cells; one 16B store of 8 channels per thread.
__global__ void __launch_bounds__(256)
nchw_to_nhwc_fp16(const float* __restrict__ feat, size_t dst_off, int HW)
{
    __shared__ float tile[64][33];
    int cell0 = blockIdx.x * 32;
    int c0    = blockIdx.y * 64;
    int b     = blockIdx.z;
    int lane = threadIdx.x & 31;
    int wid  = threadIdx.x >> 5;
    const float* src = feat + (size_t)b * NCH * HW;
#pragma unroll
    for (int k = 0; k < 8; k++) {
        int r = wid + k * 8;
        tile[r][lane] = src[(size_t)(c0 + r) * HW + cell0 + lane];
    }
    __syncthreads();
    int cell = threadIdx.x >> 3;
    int c8   = threadIdx.x & 7;
    uint4 u;
    __half2 h;
    h = __floats2half2_rn(tile[c8*8+0][cell], tile[c8*8+1][cell]); u.x = *(unsigned*)&h;
    h = __floats2half2_rn(tile[c8*8+2][cell], tile[c8*8+3][cell]); u.y = *(unsigned*)&h;
    h = __floats2half2_rn(tile[c8*8+4][cell], tile[c8*8+5][cell]); u.z = *(unsigned*)&h;
    h = __floats2half2_rn(tile[c8*8+6][cell], tile[c8*8+7][cell]); u.w = *(unsigned*)&h;
    size_t addr = ((size_t)b * HW + cell0 + cell) * NCH + c0 + c8 * 8;
    reinterpret_cast<uint4*>(g_nhwc + dst_off)[addr >> 3] = u;
}

// ---------------------------------------------------------------------------
// Gather: one warp = one output pixel, lanes cover 256 channels (8 fp16 each;
// one 16B load per tap). Each bilinear sample accumulates its 4 taps in
// __half2 chains (HFMA2, first tap HMUL2); the 4 sample chains combine via an
// HADD2 tree; widened to fp32 ONCE per pixel (8 cvt). Geometry recomputed
// in-kernel.

#define TAP0(ptr, wh, s0, s1, s2, s3) do {                                   \
    uint4 _v = __ldg(reinterpret_cast<const uint4*>(ptr));                   \
    const __half2* _h = reinterpret_cast<const __half2*>(&_v);               \
    s0 = __hmul2(wh, _h[0]); s1 = __hmul2(wh, _h[1]);                        \
    s2 = __hmul2(wh, _h[2]); s3 = __hmul2(wh, _h[3]);                        \
} while (0)

#define TAPH(ptr, wh, s0, s1, s2, s3) do {                                   \
    uint4 _v = __ldg(reinterpret_cast<const uint4*>(ptr));                   \
    const __half2* _h = reinterpret_cast<const __half2*>(&_v);               \
    s0 = __hfma2(wh, _h[0], s0); s1 = __hfma2(wh, _h[1], s1);                \
    s2 = __hfma2(wh, _h[2], s2); s3 = __hfma2(wh, _h[3], s3);                \
} while (0)

template <int P, int H, int W>
__device__ __forceinline__ void gather_level(
    const float* __restrict__ rois, float* __restrict__ out_lvl,
    size_t lvl_off, float scale, int pxbase, int npx, float* __restrict__ sacc)
{
    constexpr int pixels = P * P;
    int tid  = threadIdx.x;
    int wid  = tid >> 5;
    int lane = tid & 31;

    for (int j = 0; j < 4; j++) {
        int pxl = j * 8 + wid;
        int gpx = pxbase + pxl;
        float accf[8] = {0.f,0.f,0.f,0.f,0.f,0.f,0.f,0.f};
        if (gpx < npx) {
            int n  = gpx / pixels;
            int p  = gpx - n * pixels;
            int ph = p / P;
            int pw = p - ph * P;
            const float* r = rois + n * 5;
            int   bi = (int)r[0];
            float x1 = fmaf(r[1], scale, -0.5f);
            float y1 = fmaf(r[2], scale, -0.5f);
            float bw = (fmaf(r[3], scale, -0.5f) - x1) * (1.0f / (float)P);
            float bh = (fmaf(r[4], scale, -0.5f) - y1) * (1.0f / (float)P);
            const __half* img = g_nhwc + lvl_off
                              + (size_t)bi * ((size_t)H * W) * NCH + lane * 8;

            __half2 c0[4], c1[4], c2[4], c3[4];   // one 4-tap chain per sample
#pragma unroll
            for (int iy = 0; iy < 2; iy++) {
#pragma unroll
                for (int ix = 0; ix < 2; ix++) {
                    float yy = fmaf((float)ph + 0.25f + 0.5f * iy, bh, y1);
                    float xx = fmaf((float)pw + 0.25f + 0.5f * ix, bw, x1);
                    bool valid = (yy > -1.f) && (yy < (float)H) &&
                                 (xx > -1.f) && (xx < (float)W);
                    float yc = fminf(fmaxf(yy, 0.f), (float)(H - 1));
                    float xc = fminf(fmaxf(xx, 0.f), (float)(W - 1));
                    int y0 = (int)yc;
                    int x0 = (int)xc;
                    float wy1 = (y0 >= H - 1) ? 1.f : yc - (float)y0;
                    float wx1 = (x0 >= W - 1) ? 1.f : xc - (float)x0;
                    int ya = min(y0, H - 2);
                    int xa = min(x0, W - 2);
                    float ws  = valid ? 0.25f : 0.f;
                    __half2 w00 = __float2half2_rn((1.f - wy1) * (1.f - wx1) * ws);
                    __half2 w01 = __float2half2_rn((1.f - wy1) * wx1 * ws);
                    __half2 w10 = __float2half2_rn(wy1 * (1.f - wx1) * ws);
                    __half2 w11 = __float2half2_rn(wy1 * wx1 * ws);
                    const __half* f = img + (size_t)(ya * W + xa) * NCH;
                    __half2 *s0, *s1, *s2, *s3;
                    int s = iy * 2 + ix;
                    if (s == 0)      { s0=&c0[0]; s1=&c0[1]; s2=&c0[2]; s3=&c0[3]; }
                    else if (s == 1) { s0=&c1[0]; s1=&c1[1]; s2=&c1[2]; s3=&c1[3]; }
                    else if (s == 2) { s0=&c2[0]; s1=&c2[1]; s2=&c2[2]; s3=&c2[3]; }
                    else             { s0=&c3[0]; s1=&c3[1]; s2=&c3[2]; s3=&c3[3]; }
                    TAP0(f,                       w00, *s0, *s1, *s2, *s3);
                    TAPH(f + NCH,                 w01, *s0, *s1, *s2, *s3);
                    TAPH(f + (size_t)W * NCH,     w10, *s0, *s1, *s2, *s3);
                    TAPH(f + (size_t)(W+1) * NCH, w11, *s0, *s1, *s2, *s3);
                }
            }
            // HADD2 tree + single widen per pixel
#pragma unroll
            for (int rgi = 0; rgi < 4; rgi++) {
                __half2 u = __hadd2(c0[rgi], c1[rgi]);
                __half2 v = __hadd2(c2[rgi], c3[rgi]);
                __half2 t = __hadd2(u, v);
                accf[rgi * 2 + 0] = __low2float(t);
                accf[rgi * 2 + 1] = __high2float(t);
            }
        }
        int col = pxl ^ lane;
#pragma unroll
        for (int i = 0; i < 8; i++)
            sacc[(lane * 8 + i) * 32 + col] = accf[i];
    }
    __syncthreads();

    int pxlane = tid & 31;
    int gpx = pxbase + pxlane;
    if (gpx < npx) {
        int n = gpx / pixels;
        int p = gpx - n * pixels;
        float* ob = out_lvl + (size_t)n * NCH * pixels + p;
        int c0i = (tid >> 5) * 32;
#pragma unroll
        for (int i = 0; i < 32; i++) {
            int c = c0i + i;
            ob[(size_t)c * pixels] = sacc[c * 32 + (pxlane ^ ((c >> 3) & 31))];
        }
    }
}

__global__ void __launch_bounds__(256)
roi_gather_kernel(const float* __restrict__ rois, float* __restrict__ out,
                  int N, int nb1, int nb2)
{
    __shared__ float sacc[NCH * 32];
    int blk = blockIdx.x;
    if (blk < nb1) {
        gather_level<28, 256, 256>(rois, out, 0ull, 0.25f,
                                   blk * 32, N * 784, sacc);
    } else if (blk < nb1 + nb2) {
        float* o2 = out + (size_t)N * NCH * 784;
        gather_level<14, 128, 128>(rois, o2, 33554432ull, 0.125f,
                                   (blk - nb1) * 32, N * 196, sacc);
    } else {
        float* o3 = out + (size_t)N * NCH * (784 + 196);
        gather_level<7, 64, 64>(rois, o3, 41943040ull, 0.0625f,
                                (blk - nb1 - nb2) * 32, N * 49, sacc);
    }
}

// ---------------------------------------------------------------------------
extern "C" void kernel_launch(void* const* d_in, const int* in_sizes, int n_in,
                              void* d_out, int out_size)
{
    const float* feat1 = (const float*)d_in[0];  // (2,256,256,256)
    const float* feat2 = (const float*)d_in[1];  // (2,256,128,128)
    const float* feat3 = (const float*)d_in[2];  // (2,256,64,64)
    const float* rois  = (const float*)d_in[3];  // (N,5)
    float* out = (float*)d_out;

    const int N = in_sizes[3] / 5;

    // 1) transpose each level to fp16 NHWC scratch (R4 version)
    {
        dim3 g1(65536 / 32, 4, 2);
        nchw_to_nhwc_fp16<<<g1, 256>>>(feat1, 0ull, 65536);
        dim3 g2(16384 / 32, 4, 2);
        nchw_to_nhwc_fp16<<<g2, 256>>>(feat2, 33554432ull, 16384);
        dim3 g3(4096 / 32, 4, 2);
        nchw_to_nhwc_fp16<<<g3, 256>>>(feat3, 41943040ull, 4096);
    }

    // 2) fused gather over all three levels
    int nb1 = (N * 784 + 31) / 32;
    int nb2 = (N * 196 + 31) / 32;
    int nb3 = (N * 49  + 31) / 32;
    roi_gather_kernel<<<nb1 + nb2 + nb3, 256>>>(rois, out, N, nb1, nb2);
}